// round 1
// baseline (speedup 1.0000x reference)
#include <cuda_runtime.h>
#include <cstdint>

#define NEG_SLOPE 0.2f

static constexpr int MAXN = 50000;
static constexpr int MAXE = 800000;
static constexpr int CIN  = 128;
static constexpr int CHID = 256;
static constexpr int COUT = 128;
static constexpr int ED   = 8;

// ---------------- scratch (static device globals; no allocation allowed) ---
__device__ int   d_deg[MAXN];
__device__ int   d_row[MAXN + 1];
__device__ int   d_cur[MAXN];
__device__ int   d_csr_src[MAXE];
__device__ int   d_csr_dst[MAXE];
__device__ float d_csr_ea[(size_t)MAXE * ED];
__device__ float d_csr_alpha[MAXE];
__device__ float d_h[(size_t)MAXN * CHID];      // current layer's transformed feats
__device__ float d_hidden[(size_t)MAXN * CHID]; // relu(out of layer1)
__device__ float d_as[MAXN];
__device__ float d_ad[MAXN];
__device__ float d_easum[ED];
__device__ float d_v[ED];
__device__ float d_loopae;

// ---------------- small helpers -------------------------------------------
__global__ void zero_kernel(int n) {
    for (int i = blockIdx.x * blockDim.x + threadIdx.x; i < n;
         i += gridDim.x * blockDim.x)
        d_deg[i] = 0;
    if (blockIdx.x == 0 && threadIdx.x < ED) d_easum[threadIdx.x] = 0.f;
}

// histogram of dst degrees + per-feature sum of edge_attr
__global__ void hist_kernel(const int* __restrict__ dstp,
                            const float* __restrict__ ea, int E) {
    __shared__ float ss[ED];
    if (threadIdx.x < ED) ss[threadIdx.x] = 0.f;
    __syncthreads();
    float ls[ED] = {};
    for (int i = blockIdx.x * blockDim.x + threadIdx.x; i < E;
         i += gridDim.x * blockDim.x) {
        atomicAdd(&d_deg[dstp[i]], 1);
        const float4* p = (const float4*)(ea + (size_t)i * ED);
        float4 a = p[0], b = p[1];
        ls[0] += a.x; ls[1] += a.y; ls[2] += a.z; ls[3] += a.w;
        ls[4] += b.x; ls[5] += b.y; ls[6] += b.z; ls[7] += b.w;
    }
#pragma unroll
    for (int k = 0; k < ED; k++) atomicAdd(&ss[k], ls[k]);
    __syncthreads();
    if (threadIdx.x < ED) atomicAdd(&d_easum[threadIdx.x], ss[threadIdx.x]);
}

// single-block exclusive scan of d_deg -> d_row / d_cur
__global__ void scan_kernel(int n) {
    __shared__ int partial[1024];
    const int t = threadIdx.x;
    const int CHK = (n + 1023) / 1024;
    int start = t * CHK;
    int end = start + CHK; if (end > n) end = n;
    int s = 0;
    for (int i = start; i < end; i++) s += d_deg[i];
    partial[t] = s;
    __syncthreads();
    for (int off = 1; off < 1024; off <<= 1) {
        int v = (t >= off) ? partial[t - off] : 0;
        __syncthreads();
        partial[t] += v;
        __syncthreads();
    }
    int run = (t == 0) ? 0 : partial[t - 1];
    for (int i = start; i < end; i++) {
        d_row[i] = run;
        d_cur[i] = run;
        run += d_deg[i];
    }
    if (t == 1023) d_row[n] = partial[1023];
}

// scatter edges into CSR-by-dst; permute edge_attr alongside
__global__ void scatter_kernel(const int* __restrict__ srcp,
                               const int* __restrict__ dstp,
                               const float* __restrict__ ea, int E) {
    for (int e = blockIdx.x * blockDim.x + threadIdx.x; e < E;
         e += gridDim.x * blockDim.x) {
        int d = dstp[e];
        int pos = atomicAdd(&d_cur[d], 1);
        d_csr_src[pos] = srcp[e];
        d_csr_dst[pos] = d;
        const float4* p = (const float4*)(ea + (size_t)e * ED);
        float4* q = (float4*)(d_csr_ea + (size_t)pos * ED);
        q[0] = p[0];
        q[1] = p[1];
    }
}

// v = We @ a_edge  (v[ED]);  loop_ae = mean(edge_attr) . v
template <int C>
__global__ void compute_v_kernel(const float* __restrict__ We,
                                 const float* __restrict__ aev, float Einv) {
    int wid = threadIdx.x >> 5, lane = threadIdx.x & 31;
    if (wid < ED) {
        float s = 0.f;
        for (int c = lane; c < C; c += 32) s += We[wid * C + c] * aev[c];
        for (int o = 16; o; o >>= 1) s += __shfl_xor_sync(~0u, s, o);
        if (!lane) d_v[wid] = s;
    }
    __syncthreads();
    if (threadIdx.x == 0) {
        float la = 0.f;
#pragma unroll
        for (int i = 0; i < ED; i++) la += d_easum[i] * Einv * d_v[i];
        d_loopae = la;
    }
}

// ---------------- GEMM: C[M,N] = A[M,K] @ B[K,N], row-major, fp32 ----------
__global__ void sgemm_kernel(const float* __restrict__ A,
                             const float* __restrict__ B,
                             float* __restrict__ C, int M, int N, int K) {
    constexpr int BM = 64, BN = 64, BK = 16, TM = 4, TN = 4;
    __shared__ float As[BK][BM];
    __shared__ float Bs[BK][BN];
    const int tid = threadIdx.x;            // 256 threads
    const int brow = blockIdx.y, bcol = blockIdx.x;
    const int threadRow = tid / (BN / TN);  // 0..15
    const int threadCol = tid % (BN / TN);  // 0..15
    const int aRow = tid / (BK / 4);        // 0..63
    const int aCol = (tid % (BK / 4)) * 4;  // 0,4,8,12
    const int bRow = tid / (BN / 4);        // 0..15
    const int bCol = (tid % (BN / 4)) * 4;  // 0..60
    float acc[TM][TN] = {};
    const float* Ab = A + (size_t)brow * BM * K;
    const float* Bb = B + bcol * BN;
    const int gARow = brow * BM + aRow;
    for (int k0 = 0; k0 < K; k0 += BK) {
        float4 av = (gARow < M)
                        ? *(const float4*)(Ab + (size_t)aRow * K + k0 + aCol)
                        : make_float4(0.f, 0.f, 0.f, 0.f);
        As[aCol + 0][aRow] = av.x;
        As[aCol + 1][aRow] = av.y;
        As[aCol + 2][aRow] = av.z;
        As[aCol + 3][aRow] = av.w;
        *(float4*)&Bs[bRow][bCol] =
            *(const float4*)(Bb + (size_t)(k0 + bRow) * N + bCol);
        __syncthreads();
#pragma unroll
        for (int k = 0; k < BK; k++) {
            float ar[TM], br[TN];
#pragma unroll
            for (int i = 0; i < TM; i++) ar[i] = As[k][threadRow * TM + i];
#pragma unroll
            for (int j = 0; j < TN; j++) br[j] = Bs[k][threadCol * TN + j];
#pragma unroll
            for (int i = 0; i < TM; i++)
#pragma unroll
                for (int j = 0; j < TN; j++) acc[i][j] += ar[i] * br[j];
        }
        __syncthreads();
    }
#pragma unroll
    for (int i = 0; i < TM; i++) {
        int r = brow * BM + threadRow * TM + i;
        if (r < M) {
            float4 o = make_float4(acc[i][0], acc[i][1], acc[i][2], acc[i][3]);
            *(float4*)(C + (size_t)r * N + bcol * BN + threadCol * TN) = o;
        }
    }
}

// ---------------- per-node attention dots ----------------------------------
template <int C>
__global__ void node_dots_kernel(const float* __restrict__ h,
                                 const float* __restrict__ av,
                                 const float* __restrict__ dv, int N) {
    int warp = (blockIdx.x * blockDim.x + threadIdx.x) >> 5;
    int lane = threadIdx.x & 31;
    if (warp >= N) return;
    const float* hr = h + (size_t)warp * C;
    float s = 0.f, d = 0.f;
#pragma unroll
    for (int i = lane; i < C; i += 32) {
        float x = hr[i];
        s += x * av[i];
        d += x * dv[i];
    }
    for (int o = 16; o; o >>= 1) {
        s += __shfl_xor_sync(~0u, s, o);
        d += __shfl_xor_sync(~0u, d, o);
    }
    if (!lane) {
        d_as[warp] = s;
        d_ad[warp] = d;
    }
}

// ---------------- per-edge alpha (leaky relu of attention logits) ----------
__global__ void edge_alpha_kernel(int E) {
    float v0 = d_v[0], v1 = d_v[1], v2 = d_v[2], v3 = d_v[3];
    float v4 = d_v[4], v5 = d_v[5], v6 = d_v[6], v7 = d_v[7];
    for (int i = blockIdx.x * blockDim.x + threadIdx.x; i < E;
         i += gridDim.x * blockDim.x) {
        int s = d_csr_src[i], d = d_csr_dst[i];
        const float4* ea = (const float4*)(d_csr_ea + (size_t)i * ED);
        float4 e0 = ea[0], e1 = ea[1];
        float aev = e0.x * v0 + e0.y * v1 + e0.z * v2 + e0.w * v3 +
                    e1.x * v4 + e1.y * v5 + e1.z * v6 + e1.w * v7;
        float a = d_as[s] + d_ad[d] + aev;
        d_csr_alpha[i] = a > 0.f ? a : NEG_SLOPE * a;
    }
}

// ---------------- warp-per-node softmax + weighted aggregation -------------
template <int C, bool RELU>
__global__ void aggregate_kernel(const float* __restrict__ h,
                                 const float* __restrict__ bias,
                                 float* __restrict__ out, int N) {
    int warp = (blockIdx.x * blockDim.x + threadIdx.x) >> 5;
    int lane = threadIdx.x & 31;
    if (warp >= N) return;
    const int n = warp;
    const int rs = d_row[n], re = d_row[n + 1];
    float aself = d_as[n] + d_ad[n] + d_loopae;
    aself = aself > 0.f ? aself : NEG_SLOPE * aself;
    // max over segment (incl. self loop)
    float m = aself;
    for (int j = rs + lane; j < re; j += 32) m = fmaxf(m, d_csr_alpha[j]);
    for (int o = 16; o; o >>= 1) m = fmaxf(m, __shfl_xor_sync(~0u, m, o));
    // sum of exp
    float ssum = 0.f;
    for (int j = rs + lane; j < re; j += 32)
        ssum += __expf(d_csr_alpha[j] - m);
    for (int o = 16; o; o >>= 1) ssum += __shfl_xor_sync(~0u, ssum, o);
    float wself = __expf(aself - m);
    float inv = 1.f / (ssum + wself);

    constexpr int V = C / 128;  // float4s per lane
    float4 acc[V];
    {
        const float4* hn = (const float4*)(h + (size_t)n * C);
        float w = wself * inv;
#pragma unroll
        for (int k = 0; k < V; k++) {
            float4 hv = hn[lane + 32 * k];
            acc[k] = make_float4(hv.x * w, hv.y * w, hv.z * w, hv.w * w);
        }
    }
    for (int j = rs; j < re; j++) {
        float a = d_csr_alpha[j];   // warp-broadcast load
        int s = d_csr_src[j];
        float w = __expf(a - m) * inv;
        const float4* hs = (const float4*)(h + (size_t)s * C);
#pragma unroll
        for (int k = 0; k < V; k++) {
            float4 hv = hs[lane + 32 * k];
            acc[k].x += w * hv.x;
            acc[k].y += w * hv.y;
            acc[k].z += w * hv.z;
            acc[k].w += w * hv.w;
        }
    }
    const float4* bp = (const float4*)bias;
    float4* op = (float4*)(out + (size_t)n * C);
#pragma unroll
    for (int k = 0; k < V; k++) {
        float4 b = bp[lane + 32 * k];
        float4 o = make_float4(acc[k].x + b.x, acc[k].y + b.y,
                               acc[k].z + b.z, acc[k].w + b.w);
        if (RELU) {
            o.x = fmaxf(o.x, 0.f);
            o.y = fmaxf(o.y, 0.f);
            o.z = fmaxf(o.z, 0.f);
            o.w = fmaxf(o.w, 0.f);
        }
        op[lane + 32 * k] = o;
    }
}

// ---------------- launch ----------------------------------------------------
extern "C" void kernel_launch(void* const* d_in, const int* in_sizes, int n_in,
                              void* d_out, int out_size) {
    const float* x   = (const float*)d_in[0];
    const int*   ei  = (const int*)d_in[1];
    const float* ea  = (const float*)d_in[2];
    const float* W1  = (const float*)d_in[3];
    const float* We1 = (const float*)d_in[4];
    const float* as1 = (const float*)d_in[5];
    const float* ad1 = (const float*)d_in[6];
    const float* ae1 = (const float*)d_in[7];
    const float* b1  = (const float*)d_in[8];
    const float* W2  = (const float*)d_in[9];
    const float* We2 = (const float*)d_in[10];
    const float* as2 = (const float*)d_in[11];
    const float* ad2 = (const float*)d_in[12];
    const float* ae2 = (const float*)d_in[13];
    const float* b2  = (const float*)d_in[14];
    float* out = (float*)d_out;

    const int E = in_sizes[2] / ED;
    const int N = in_sizes[0] / CIN;
    const int* srcp = ei;
    const int* dstp = ei + E;

    void* p;
    cudaGetSymbolAddress(&p, d_h);      float* hbuf   = (float*)p;
    cudaGetSymbolAddress(&p, d_hidden); float* hidbuf = (float*)p;

    const int TPB = 256;
    const int warpsPerBlock = TPB / 32;
    const int nodeBlocks = (N + warpsPerBlock - 1) / warpsPerBlock;

    // ---- graph structure build (every launch; deterministic work) ----
    zero_kernel<<<256, TPB>>>(N);
    hist_kernel<<<512, TPB>>>(dstp, ea, E);
    scan_kernel<<<1, 1024>>>(N);
    scatter_kernel<<<512, TPB>>>(srcp, dstp, ea, E);

    // ---- layer 1 ----
    {
        dim3 g(CHID / 64, (N + 63) / 64);
        sgemm_kernel<<<g, TPB>>>(x, W1, hbuf, N, CHID, CIN);
        node_dots_kernel<CHID><<<nodeBlocks, TPB>>>(hbuf, as1, ad1, N);
        compute_v_kernel<CHID><<<1, 256>>>(We1, ae1, 1.f / (float)E);
        edge_alpha_kernel<<<512, TPB>>>(E);
        aggregate_kernel<CHID, true><<<nodeBlocks, TPB>>>(hbuf, b1, hidbuf, N);
    }
    // ---- layer 2 ----
    {
        dim3 g(COUT / 64, (N + 63) / 64);
        sgemm_kernel<<<g, TPB>>>(hidbuf, W2, hbuf, N, COUT, CHID);
        node_dots_kernel<COUT><<<nodeBlocks, TPB>>>(hbuf, as2, ad2, N);
        compute_v_kernel<COUT><<<1, 256>>>(We2, ae2, 1.f / (float)E);
        edge_alpha_kernel<<<512, TPB>>>(E);
        aggregate_kernel<COUT, false><<<nodeBlocks, TPB>>>(hbuf, b2, out, N);
    }
}

// round 2
// speedup vs baseline: 1.3734x; 1.3734x over previous
#include <cuda_runtime.h>
#include <cstdint>

#define NEG_SLOPE 0.2f

static constexpr int MAXN = 50000;
static constexpr int MAXE = 800000;
static constexpr int CIN  = 128;
static constexpr int CHID = 256;
static constexpr int COUT = 128;
static constexpr int ED   = 8;

// ---------------- scratch (static device globals; no allocation allowed) ---
__device__ int   d_deg[MAXN];
__device__ int   d_row[MAXN + 1];
__device__ int   d_cur[MAXN];
__device__ int   d_csr_src[MAXE];
__device__ float d_aev1[MAXE];
__device__ float d_aev2[MAXE];
__device__ float d_alpha[MAXE];
__device__ float d_h[(size_t)MAXN * CHID];      // current layer transformed feats
__device__ float d_hidden[(size_t)MAXN * CHID]; // relu(out of layer1)
__device__ float d_as[MAXN];
__device__ float d_ad[MAXN];
__device__ float d_easum[ED];
__device__ float d_v[2][ED];
__device__ float d_loopae[2];

// ---------------- small helpers -------------------------------------------
__global__ void zero_kernel(int n) {
    for (int i = blockIdx.x * blockDim.x + threadIdx.x; i < n;
         i += gridDim.x * blockDim.x)
        d_deg[i] = 0;
    if (blockIdx.x == 0 && threadIdx.x < ED) d_easum[threadIdx.x] = 0.f;
}

// histogram of dst degrees + per-feature sum of edge_attr
__global__ void hist_kernel(const int* __restrict__ dstp,
                            const float* __restrict__ ea, int E) {
    __shared__ float ss[ED];
    if (threadIdx.x < ED) ss[threadIdx.x] = 0.f;
    __syncthreads();
    float ls[ED] = {};
    for (int i = blockIdx.x * blockDim.x + threadIdx.x; i < E;
         i += gridDim.x * blockDim.x) {
        atomicAdd(&d_deg[dstp[i]], 1);
        const float4* p = (const float4*)(ea + (size_t)i * ED);
        float4 a = p[0], b = p[1];
        ls[0] += a.x; ls[1] += a.y; ls[2] += a.z; ls[3] += a.w;
        ls[4] += b.x; ls[5] += b.y; ls[6] += b.z; ls[7] += b.w;
    }
#pragma unroll
    for (int k = 0; k < ED; k++) atomicAdd(&ss[k], ls[k]);
    __syncthreads();
    if (threadIdx.x < ED) atomicAdd(&d_easum[threadIdx.x], ss[threadIdx.x]);
}

// single-block exclusive scan of d_deg -> d_row / d_cur
__global__ void scan_kernel(int n) {
    __shared__ int partial[1024];
    const int t = threadIdx.x;
    const int CHK = (n + 1023) / 1024;
    int start = t * CHK;
    int end = start + CHK; if (end > n) end = n;
    int s = 0;
    for (int i = start; i < end; i++) s += d_deg[i];
    partial[t] = s;
    __syncthreads();
    for (int off = 1; off < 1024; off <<= 1) {
        int v = (t >= off) ? partial[t - off] : 0;
        __syncthreads();
        partial[t] += v;
        __syncthreads();
    }
    int run = (t == 0) ? 0 : partial[t - 1];
    for (int i = start; i < end; i++) {
        d_row[i] = run;
        d_cur[i] = run;
        run += d_deg[i];
    }
    if (t == 1023) d_row[n] = partial[1023];
}

// v[l] = We_l @ ae_l ; loopae[l] = (easum/E) . v[l]   (16 warps, 512 thr)
__global__ void compute_v_kernel(const float* __restrict__ We1,
                                 const float* __restrict__ ae1,
                                 const float* __restrict__ We2,
                                 const float* __restrict__ ae2, float Einv) {
    int wid = threadIdx.x >> 5, lane = threadIdx.x & 31;
    if (wid < ED) {
        float s = 0.f;
        for (int c = lane; c < CHID; c += 32) s += We1[wid * CHID + c] * ae1[c];
        for (int o = 16; o; o >>= 1) s += __shfl_xor_sync(~0u, s, o);
        if (!lane) d_v[0][wid] = s;
    } else {
        int r = wid - ED;
        float s = 0.f;
        for (int c = lane; c < COUT; c += 32) s += We2[r * COUT + c] * ae2[c];
        for (int o = 16; o; o >>= 1) s += __shfl_xor_sync(~0u, s, o);
        if (!lane) d_v[1][r] = s;
    }
    __syncthreads();
    if (threadIdx.x < 2) {
        float la = 0.f;
#pragma unroll
        for (int i = 0; i < ED; i++)
            la += d_easum[i] * Einv * d_v[threadIdx.x][i];
        d_loopae[threadIdx.x] = la;
    }
}

// scatter edges into CSR-by-dst; compute per-edge attr-attention for both layers
__global__ void scatter_kernel(const int* __restrict__ srcp,
                               const int* __restrict__ dstp,
                               const float* __restrict__ ea, int E) {
    float v10 = d_v[0][0], v11 = d_v[0][1], v12 = d_v[0][2], v13 = d_v[0][3];
    float v14 = d_v[0][4], v15 = d_v[0][5], v16 = d_v[0][6], v17 = d_v[0][7];
    float v20 = d_v[1][0], v21 = d_v[1][1], v22 = d_v[1][2], v23 = d_v[1][3];
    float v24 = d_v[1][4], v25 = d_v[1][5], v26 = d_v[1][6], v27 = d_v[1][7];
    for (int e = blockIdx.x * blockDim.x + threadIdx.x; e < E;
         e += gridDim.x * blockDim.x) {
        int d = dstp[e];
        int pos = atomicAdd(&d_cur[d], 1);
        const float4* p = (const float4*)(ea + (size_t)e * ED);
        float4 a = p[0], b = p[1];
        float a1 = a.x * v10 + a.y * v11 + a.z * v12 + a.w * v13 +
                   b.x * v14 + b.y * v15 + b.z * v16 + b.w * v17;
        float a2 = a.x * v20 + a.y * v21 + a.z * v22 + a.w * v23 +
                   b.x * v24 + b.y * v25 + b.z * v26 + b.w * v27;
        d_csr_src[pos] = srcp[e];
        d_aev1[pos] = a1;
        d_aev2[pos] = a2;
    }
}

// ---------------- tf32 tensor-core GEMM: C[M,N]=A[M,K]@B[K,N] row-major ----
__device__ __forceinline__ uint32_t f2tf32(float x) {
    uint32_t u;
    asm("cvt.rna.tf32.f32 %0, %1;" : "=r"(u) : "f"(x));
    return u;
}
__device__ __forceinline__ void mma_tf32(float* d, const uint32_t* a,
                                         const uint32_t* b) {
    asm volatile(
        "mma.sync.aligned.m16n8k8.row.col.f32.tf32.tf32.f32 "
        "{%0,%1,%2,%3}, {%4,%5,%6,%7}, {%8,%9}, {%0,%1,%2,%3};\n"
        : "+f"(d[0]), "+f"(d[1]), "+f"(d[2]), "+f"(d[3])
        : "r"(a[0]), "r"(a[1]), "r"(a[2]), "r"(a[3]), "r"(b[0]), "r"(b[1]));
}

#define GBM 128
#define GBN 128
#define GBK 16
#define GBMP 20   // As row stride (BK + 4) -> conflict-free frag loads
#define GBNP 136  // Bs row stride (BN + 8)

__global__ __launch_bounds__(256, 2) void mma_gemm_kernel(
    const float* __restrict__ A, const float* __restrict__ B,
    float* __restrict__ C, int M, int N, int K) {
    __shared__ __align__(16) uint32_t As[2][GBM][GBMP];  // row-major [m][k]
    __shared__ __align__(16) uint32_t Bs[2][GBK][GBNP];  // [k][n]

    const int t = threadIdx.x;
    const int bm = blockIdx.y * GBM;
    const int bn = blockIdx.x * GBN;
    const int warp = t >> 5, lane = t & 31;
    const int g = lane >> 2, t4 = lane & 3;
    const int wm = (warp >> 2) * 64, wn = (warp & 3) * 32;

    // copy thread mappings
    const int arow = t >> 2, ac4 = t & 3;       // A: rows arow, arow+64
    const int brow = t >> 5, bc4 = t & 31;      // B: rows brow, brow+8

    float4 pa0, pa1, pb0, pb1;
    auto ldg = [&](int k0) {
        int r0 = bm + arow, r1 = bm + arow + 64;
        pa0 = (r0 < M) ? *(const float4*)(A + (size_t)r0 * K + k0 + ac4 * 4)
                       : make_float4(0.f, 0.f, 0.f, 0.f);
        pa1 = (r1 < M) ? *(const float4*)(A + (size_t)r1 * K + k0 + ac4 * 4)
                       : make_float4(0.f, 0.f, 0.f, 0.f);
        pb0 = *(const float4*)(B + (size_t)(k0 + brow) * N + bn + bc4 * 4);
        pb1 = *(const float4*)(B + (size_t)(k0 + brow + 8) * N + bn + bc4 * 4);
    };
    auto sts = [&](int s) {
        uint4 u;
        u.x = f2tf32(pa0.x); u.y = f2tf32(pa0.y);
        u.z = f2tf32(pa0.z); u.w = f2tf32(pa0.w);
        *(uint4*)&As[s][arow][ac4 * 4] = u;
        u.x = f2tf32(pa1.x); u.y = f2tf32(pa1.y);
        u.z = f2tf32(pa1.z); u.w = f2tf32(pa1.w);
        *(uint4*)&As[s][arow + 64][ac4 * 4] = u;
        u.x = f2tf32(pb0.x); u.y = f2tf32(pb0.y);
        u.z = f2tf32(pb0.z); u.w = f2tf32(pb0.w);
        *(uint4*)&Bs[s][brow][bc4 * 4] = u;
        u.x = f2tf32(pb1.x); u.y = f2tf32(pb1.y);
        u.z = f2tf32(pb1.z); u.w = f2tf32(pb1.w);
        *(uint4*)&Bs[s][brow + 8][bc4 * 4] = u;
    };

    float acc[4][4][4];
#pragma unroll
    for (int i = 0; i < 4; i++)
#pragma unroll
        for (int j = 0; j < 4; j++)
#pragma unroll
            for (int r = 0; r < 4; r++) acc[i][j][r] = 0.f;

    const int nIter = K / GBK;
    ldg(0);
    sts(0);
    __syncthreads();

    for (int it = 0; it < nIter; it++) {
        const int s = it & 1;
        if (it + 1 < nIter) ldg((it + 1) * GBK);
#pragma unroll
        for (int kk = 0; kk < 2; kk++) {
            uint32_t af[4][4], bf[4][2];
#pragma unroll
            for (int i = 0; i < 4; i++) {
                int r0 = wm + i * 16 + g;
                af[i][0] = As[s][r0][kk * 8 + t4];
                af[i][1] = As[s][r0 + 8][kk * 8 + t4];
                af[i][2] = As[s][r0][kk * 8 + t4 + 4];
                af[i][3] = As[s][r0 + 8][kk * 8 + t4 + 4];
            }
#pragma unroll
            for (int j = 0; j < 4; j++) {
                bf[j][0] = Bs[s][kk * 8 + t4][wn + j * 8 + g];
                bf[j][1] = Bs[s][kk * 8 + t4 + 4][wn + j * 8 + g];
            }
#pragma unroll
            for (int i = 0; i < 4; i++)
#pragma unroll
                for (int j = 0; j < 4; j++) mma_tf32(acc[i][j], af[i], bf[j]);
        }
        if (it + 1 < nIter) {
            sts(s ^ 1);
            __syncthreads();
        }
    }

    // epilogue
#pragma unroll
    for (int i = 0; i < 4; i++) {
        int r0 = bm + wm + i * 16 + g;
        int r1 = r0 + 8;
#pragma unroll
        for (int j = 0; j < 4; j++) {
            int c = bn + wn + j * 8 + 2 * t4;
            if (r0 < M)
                *(float2*)(C + (size_t)r0 * N + c) =
                    make_float2(acc[i][j][0], acc[i][j][1]);
            if (r1 < M)
                *(float2*)(C + (size_t)r1 * N + c) =
                    make_float2(acc[i][j][2], acc[i][j][3]);
        }
    }
}

// ---------------- per-node attention dots ----------------------------------
template <int C>
__global__ void node_dots_kernel(const float* __restrict__ h,
                                 const float* __restrict__ av,
                                 const float* __restrict__ dv, int N) {
    int warp = (blockIdx.x * blockDim.x + threadIdx.x) >> 5;
    int lane = threadIdx.x & 31;
    if (warp >= N) return;
    const float* hr = h + (size_t)warp * C;
    float s = 0.f, d = 0.f;
#pragma unroll
    for (int i = lane; i < C; i += 32) {
        float x = hr[i];
        s += x * av[i];
        d += x * dv[i];
    }
    for (int o = 16; o; o >>= 1) {
        s += __shfl_xor_sync(~0u, s, o);
        d += __shfl_xor_sync(~0u, d, o);
    }
    if (!lane) {
        d_as[warp] = s;
        d_ad[warp] = d;
    }
}

// ---------------- per-edge partial alpha: as[src] + aev --------------------
__global__ void edge_partial_kernel(const float* __restrict__ aev, int E) {
    for (int i = blockIdx.x * blockDim.x + threadIdx.x; i < E;
         i += gridDim.x * blockDim.x)
        d_alpha[i] = d_as[d_csr_src[i]] + aev[i];
}

__device__ __forceinline__ float leaky(float x) {
    return fmaxf(x, NEG_SLOPE * x);
}

// ---------------- warp-per-node softmax + weighted aggregation -------------
template <int C, bool RELU>
__global__ void aggregate_kernel(const float* __restrict__ h,
                                 const float* __restrict__ bias,
                                 float* __restrict__ out, int N, int layer) {
    int warp = (blockIdx.x * blockDim.x + threadIdx.x) >> 5;
    int lane = threadIdx.x & 31;
    if (warp >= N) return;
    const int n = warp;
    const int rs = d_row[n], re = d_row[n + 1];
    const float adn = d_ad[n];
    float aself = leaky(d_as[n] + adn + d_loopae[layer]);
    // max over raw partials (leaky monotonic)
    float mraw = -3.4e38f;
    for (int j = rs + lane; j < re; j += 32) mraw = fmaxf(mraw, d_alpha[j]);
    for (int o = 16; o; o >>= 1) mraw = fmaxf(mraw, __shfl_xor_sync(~0u, mraw, o));
    float m = fmaxf(aself, leaky(mraw + adn));
    // sum of exp
    float ssum = 0.f;
    for (int j = rs + lane; j < re; j += 32)
        ssum += __expf(leaky(d_alpha[j] + adn) - m);
    for (int o = 16; o; o >>= 1) ssum += __shfl_xor_sync(~0u, ssum, o);
    float wself = __expf(aself - m);
    float inv = 1.f / (ssum + wself);

    constexpr int V = C / 128;  // float4s per lane
    float4 acc[V];
    {
        const float4* hn = (const float4*)(h + (size_t)n * C);
        float w = wself * inv;
#pragma unroll
        for (int k = 0; k < V; k++) {
            float4 hv = hn[lane + 32 * k];
            acc[k] = make_float4(hv.x * w, hv.y * w, hv.z * w, hv.w * w);
        }
    }
    for (int j = rs; j < re; j++) {
        float a = d_alpha[j];  // warp-broadcast load
        int s = d_csr_src[j];
        float w = __expf(leaky(a + adn) - m) * inv;
        const float4* hs = (const float4*)(h + (size_t)s * C);
#pragma unroll
        for (int k = 0; k < V; k++) {
            float4 hv = hs[lane + 32 * k];
            acc[k].x += w * hv.x;
            acc[k].y += w * hv.y;
            acc[k].z += w * hv.z;
            acc[k].w += w * hv.w;
        }
    }
    const float4* bp = (const float4*)bias;
    float4* op = (float4*)(out + (size_t)n * C);
#pragma unroll
    for (int k = 0; k < V; k++) {
        float4 b = bp[lane + 32 * k];
        float4 o = make_float4(acc[k].x + b.x, acc[k].y + b.y,
                               acc[k].z + b.z, acc[k].w + b.w);
        if (RELU) {
            o.x = fmaxf(o.x, 0.f);
            o.y = fmaxf(o.y, 0.f);
            o.z = fmaxf(o.z, 0.f);
            o.w = fmaxf(o.w, 0.f);
        }
        op[lane + 32 * k] = o;
    }
}

// ---------------- launch ----------------------------------------------------
extern "C" void kernel_launch(void* const* d_in, const int* in_sizes, int n_in,
                              void* d_out, int out_size) {
    const float* x   = (const float*)d_in[0];
    const int*   ei  = (const int*)d_in[1];
    const float* ea  = (const float*)d_in[2];
    const float* W1  = (const float*)d_in[3];
    const float* We1 = (const float*)d_in[4];
    const float* as1 = (const float*)d_in[5];
    const float* ad1 = (const float*)d_in[6];
    const float* ae1 = (const float*)d_in[7];
    const float* b1  = (const float*)d_in[8];
    const float* W2  = (const float*)d_in[9];
    const float* We2 = (const float*)d_in[10];
    const float* as2 = (const float*)d_in[11];
    const float* ad2 = (const float*)d_in[12];
    const float* ae2 = (const float*)d_in[13];
    const float* b2  = (const float*)d_in[14];
    float* out = (float*)d_out;

    const int E = in_sizes[2] / ED;
    const int N = in_sizes[0] / CIN;
    const int* srcp = ei;
    const int* dstp = ei + E;

    void* p;
    cudaGetSymbolAddress(&p, d_h);      float* hbuf   = (float*)p;
    cudaGetSymbolAddress(&p, d_hidden); float* hidbuf = (float*)p;
    cudaGetSymbolAddress(&p, d_aev1);   float* aev1p  = (float*)p;
    cudaGetSymbolAddress(&p, d_aev2);   float* aev2p  = (float*)p;

    const int TPB = 256;
    const int warpsPerBlock = TPB / 32;
    const int nodeBlocks = (N + warpsPerBlock - 1) / warpsPerBlock;

    // ---- graph structure build ----
    zero_kernel<<<256, TPB>>>(N);
    hist_kernel<<<512, TPB>>>(dstp, ea, E);
    scan_kernel<<<1, 1024>>>(N);
    compute_v_kernel<<<1, 512>>>(We1, ae1, We2, ae2, 1.f / (float)E);
    scatter_kernel<<<512, TPB>>>(srcp, dstp, ea, E);

    // ---- layer 1 ----
    {
        dim3 g(CHID / GBN, (N + GBM - 1) / GBM);
        mma_gemm_kernel<<<g, 256>>>(x, W1, hbuf, N, CHID, CIN);
        node_dots_kernel<CHID><<<nodeBlocks, TPB>>>(hbuf, as1, ad1, N);
        edge_partial_kernel<<<512, TPB>>>(aev1p, E);
        aggregate_kernel<CHID, true><<<nodeBlocks, TPB>>>(hbuf, b1, hidbuf, N, 0);
    }
    // ---- layer 2 ----
    {
        dim3 g(COUT / GBN, (N + GBM - 1) / GBM);
        mma_gemm_kernel<<<g, 256>>>(hidbuf, W2, hbuf, N, COUT, CHID);
        node_dots_kernel<COUT><<<nodeBlocks, TPB>>>(hbuf, as2, ad2, N);
        edge_partial_kernel<<<512, TPB>>>(aev2p, E);
        aggregate_kernel<COUT, false><<<nodeBlocks, TPB>>>(hbuf, b2, out, N, 1);
    }
}

// round 4
// speedup vs baseline: 1.4150x; 1.0303x over previous
#include <cuda_runtime.h>
#include <cstdint>

#define NEG_SLOPE 0.2f

static constexpr int MAXN = 50000;
static constexpr int MAXE = 800000;
static constexpr int CIN  = 128;
static constexpr int CHID = 256;
static constexpr int COUT = 128;
static constexpr int ED   = 8;

// ---------------- scratch (static device globals; no allocation allowed) ---
__device__ int   d_deg[MAXN];
__device__ int   d_row[MAXN + 1];
__device__ int   d_cur[MAXN];
__device__ int   d_csr_src[MAXE];
__device__ float d_tmpa[MAXE];   // edge-ordered aev1
__device__ float d_tmpb[MAXE];   // edge-ordered aev2
__device__ float d_aev1[MAXE];   // CSR-ordered
__device__ float d_aev2[MAXE];
__device__ float d_alpha[MAXE];
__device__ float d_h[(size_t)MAXN * CHID];
__device__ float d_hidden[(size_t)MAXN * CHID];
__device__ float d_as1[MAXN];
__device__ float d_ad1[MAXN];
__device__ float d_as2[MAXN];
__device__ float d_ad2[MAXN];
__device__ float d_easum[ED];
__device__ float d_v[2][ED];
__device__ float d_loopae[2];

// ---------------- zero + compute v (MUST run with >=512 threads/block) -----
__global__ void zero_v_kernel(const float* __restrict__ We1,
                              const float* __restrict__ ae1,
                              const float* __restrict__ We2,
                              const float* __restrict__ ae2, int n) {
    for (int i = blockIdx.x * blockDim.x + threadIdx.x; i < n;
         i += gridDim.x * blockDim.x) {
        d_deg[i] = 0;
        d_as1[i] = 0.f; d_ad1[i] = 0.f;
        d_as2[i] = 0.f; d_ad2[i] = 0.f;
    }
    if (blockIdx.x == 0) {
        if (threadIdx.x < ED) d_easum[threadIdx.x] = 0.f;
        int wid = threadIdx.x >> 5, lane = threadIdx.x & 31;
        if (wid < ED) {
            float s = 0.f;
            for (int c = lane; c < CHID; c += 32) s += We1[wid * CHID + c] * ae1[c];
            for (int o = 16; o; o >>= 1) s += __shfl_xor_sync(~0u, s, o);
            if (!lane) d_v[0][wid] = s;
        } else if (wid < 2 * ED) {
            int r = wid - ED;
            float s = 0.f;
            for (int c = lane; c < COUT; c += 32) s += We2[r * COUT + c] * ae2[c];
            for (int o = 16; o; o >>= 1) s += __shfl_xor_sync(~0u, s, o);
            if (!lane) d_v[1][r] = s;
        }
    }
}

// histogram of dst degrees + easum + per-edge attr attention (both layers)
__global__ void hist_kernel(const int* __restrict__ dstp,
                            const float* __restrict__ ea, int E) {
    __shared__ float ss[ED];
    if (threadIdx.x < ED) ss[threadIdx.x] = 0.f;
    __syncthreads();
    float v1[ED], v2[ED];
#pragma unroll
    for (int k = 0; k < ED; k++) { v1[k] = d_v[0][k]; v2[k] = d_v[1][k]; }
    float ls[ED] = {};
    for (int i = blockIdx.x * blockDim.x + threadIdx.x; i < E;
         i += gridDim.x * blockDim.x) {
        atomicAdd(&d_deg[dstp[i]], 1);
        const float4* p = (const float4*)(ea + (size_t)i * ED);
        float4 a = p[0], b = p[1];
        ls[0] += a.x; ls[1] += a.y; ls[2] += a.z; ls[3] += a.w;
        ls[4] += b.x; ls[5] += b.y; ls[6] += b.z; ls[7] += b.w;
        d_tmpa[i] = a.x * v1[0] + a.y * v1[1] + a.z * v1[2] + a.w * v1[3] +
                    b.x * v1[4] + b.y * v1[5] + b.z * v1[6] + b.w * v1[7];
        d_tmpb[i] = a.x * v2[0] + a.y * v2[1] + a.z * v2[2] + a.w * v2[3] +
                    b.x * v2[4] + b.y * v2[5] + b.z * v2[6] + b.w * v2[7];
    }
#pragma unroll
    for (int k = 0; k < ED; k++) atomicAdd(&ss[k], ls[k]);
    __syncthreads();
    if (threadIdx.x < ED) atomicAdd(&d_easum[threadIdx.x], ss[threadIdx.x]);
}

// single-block exclusive scan of d_deg -> d_row / d_cur ; + loopae
__global__ void scan_kernel(int n, float Einv) {
    __shared__ int partial[1024];
    const int t = threadIdx.x;
    const int CHK = (n + 1023) / 1024;
    int start = t * CHK;
    int end = start + CHK; if (end > n) end = n;
    int s = 0;
    for (int i = start; i < end; i++) s += d_deg[i];
    partial[t] = s;
    __syncthreads();
    for (int off = 1; off < 1024; off <<= 1) {
        int v = (t >= off) ? partial[t - off] : 0;
        __syncthreads();
        partial[t] += v;
        __syncthreads();
    }
    int run = (t == 0) ? 0 : partial[t - 1];
    for (int i = start; i < end; i++) {
        d_row[i] = run;
        d_cur[i] = run;
        run += d_deg[i];
    }
    if (t == 1023) d_row[n] = partial[1023];
    if (t < 2) {
        float la = 0.f;
#pragma unroll
        for (int i = 0; i < ED; i++) la += d_easum[i] * Einv * d_v[t][i];
        d_loopae[t] = la;
    }
}

// scatter edges into CSR-by-dst; permute precomputed aev
__global__ void scatter_kernel(const int* __restrict__ srcp,
                               const int* __restrict__ dstp, int E) {
    for (int e = blockIdx.x * blockDim.x + threadIdx.x; e < E;
         e += gridDim.x * blockDim.x) {
        int d = dstp[e];
        int pos = atomicAdd(&d_cur[d], 1);
        d_csr_src[pos] = srcp[e];
        d_aev1[pos] = d_tmpa[e];
        d_aev2[pos] = d_tmpb[e];
    }
}

// ---------------- tf32 tensor-core GEMM + fused attention dots -------------
__device__ __forceinline__ uint32_t f2tf32(float x) {
    uint32_t u;
    asm("cvt.rna.tf32.f32 %0, %1;" : "=r"(u) : "f"(x));
    return u;
}
__device__ __forceinline__ void mma_tf32(float* d, const uint32_t* a,
                                         const uint32_t* b) {
    asm volatile(
        "mma.sync.aligned.m16n8k8.row.col.f32.tf32.tf32.f32 "
        "{%0,%1,%2,%3}, {%4,%5,%6,%7}, {%8,%9}, {%0,%1,%2,%3};\n"
        : "+f"(d[0]), "+f"(d[1]), "+f"(d[2]), "+f"(d[3])
        : "r"(a[0]), "r"(a[1]), "r"(a[2]), "r"(a[3]), "r"(b[0]), "r"(b[1]));
}

// C[M,N] = A[M,K] @ B[K,N] row-major; fused dot products:
// as_out[m] += sum_c C[m,c]*av[c], ad_out[m] += sum_c C[m,c]*dv[c]
template <int BM, int BN, int WM, int WN>
__global__ __launch_bounds__(256, 2) void mma_gemm_kernel(
    const float* __restrict__ A, const float* __restrict__ B,
    float* __restrict__ C, const float* __restrict__ av,
    const float* __restrict__ dv, float* __restrict__ as_out,
    float* __restrict__ ad_out, int M, int N, int K) {
    constexpr int GBK = 16;
    constexpr int AP = GBK + 4;
    constexpr int BP = BN + 8;
    constexpr int WCOLS = BN / WN;
    constexpr int MI = WM / 16;
    constexpr int NJ = WN / 8;
    constexpr int LA = BM / 64;   // float4 per thread for A tile
    constexpr int LB = BN / 64;   // float4 per thread for B tile

    __shared__ __align__(16) uint32_t As[2][BM][AP];
    __shared__ __align__(16) uint32_t Bs[2][GBK][BP];

    const int t = threadIdx.x;
    const int bm = blockIdx.y * BM;
    const int bn = blockIdx.x * BN;
    const int warp = t >> 5, lane = t & 31;
    const int g = lane >> 2, t4 = lane & 3;
    const int wm = (warp / WCOLS) * WM, wn = (warp % WCOLS) * WN;

    float4 pa[LA], pb[LB];
    auto ldg = [&](int k0) {
#pragma unroll
        for (int r = 0; r < LA; r++) {
            int id = t + 256 * r;
            int row = id >> 2, col = (id & 3) * 4;
            int gr = bm + row;
            pa[r] = (gr < M) ? *(const float4*)(A + (size_t)gr * K + k0 + col)
                             : make_float4(0.f, 0.f, 0.f, 0.f);
        }
#pragma unroll
        for (int r = 0; r < LB; r++) {
            int id = t + 256 * r;
            int row = id / (BN / 4), col = (id % (BN / 4)) * 4;
            pb[r] = *(const float4*)(B + (size_t)(k0 + row) * N + bn + col);
        }
    };
    auto sts = [&](int s) {
#pragma unroll
        for (int r = 0; r < LA; r++) {
            int id = t + 256 * r;
            int row = id >> 2, col = (id & 3) * 4;
            uint4 u;
            u.x = f2tf32(pa[r].x); u.y = f2tf32(pa[r].y);
            u.z = f2tf32(pa[r].z); u.w = f2tf32(pa[r].w);
            *(uint4*)&As[s][row][col] = u;
        }
#pragma unroll
        for (int r = 0; r < LB; r++) {
            int id = t + 256 * r;
            int row = id / (BN / 4), col = (id % (BN / 4)) * 4;
            uint4 u;
            u.x = f2tf32(pb[r].x); u.y = f2tf32(pb[r].y);
            u.z = f2tf32(pb[r].z); u.w = f2tf32(pb[r].w);
            *(uint4*)&Bs[s][row][col] = u;
        }
    };

    float acc[MI][NJ][4];
#pragma unroll
    for (int i = 0; i < MI; i++)
#pragma unroll
        for (int j = 0; j < NJ; j++)
#pragma unroll
            for (int r = 0; r < 4; r++) acc[i][j][r] = 0.f;

    const int nIter = K / GBK;
    ldg(0);
    sts(0);
    __syncthreads();

    for (int it = 0; it < nIter; it++) {
        const int s = it & 1;
        if (it + 1 < nIter) ldg((it + 1) * GBK);
#pragma unroll
        for (int kk = 0; kk < 2; kk++) {
            uint32_t af[MI][4], bf[NJ][2];
#pragma unroll
            for (int i = 0; i < MI; i++) {
                int r0 = wm + i * 16 + g;
                af[i][0] = As[s][r0][kk * 8 + t4];
                af[i][1] = As[s][r0 + 8][kk * 8 + t4];
                af[i][2] = As[s][r0][kk * 8 + t4 + 4];
                af[i][3] = As[s][r0 + 8][kk * 8 + t4 + 4];
            }
#pragma unroll
            for (int j = 0; j < NJ; j++) {
                bf[j][0] = Bs[s][kk * 8 + t4][wn + j * 8 + g];
                bf[j][1] = Bs[s][kk * 8 + t4 + 4][wn + j * 8 + g];
            }
#pragma unroll
            for (int i = 0; i < MI; i++)
#pragma unroll
                for (int j = 0; j < NJ; j++) mma_tf32(acc[i][j], af[i], bf[j]);
        }
        if (it + 1 < nIter) {
            sts(s ^ 1);
            __syncthreads();
        }
    }

    // epilogue: store C + fused partial dots into as/ad via atomics
#pragma unroll
    for (int i = 0; i < MI; i++) {
        int r0 = bm + wm + i * 16 + g;
        int r1 = r0 + 8;
        float s0 = 0.f, d0 = 0.f, s1 = 0.f, d1 = 0.f;
#pragma unroll
        for (int j = 0; j < NJ; j++) {
            int c = bn + wn + j * 8 + 2 * t4;
            float a0 = av[c], a1 = av[c + 1];
            float e0 = dv[c], e1 = dv[c + 1];
            s0 += acc[i][j][0] * a0 + acc[i][j][1] * a1;
            d0 += acc[i][j][0] * e0 + acc[i][j][1] * e1;
            s1 += acc[i][j][2] * a0 + acc[i][j][3] * a1;
            d1 += acc[i][j][2] * e0 + acc[i][j][3] * e1;
            if (r0 < M)
                *(float2*)(C + (size_t)r0 * N + c) =
                    make_float2(acc[i][j][0], acc[i][j][1]);
            if (r1 < M)
                *(float2*)(C + (size_t)r1 * N + c) =
                    make_float2(acc[i][j][2], acc[i][j][3]);
        }
#pragma unroll
        for (int o = 1; o < 4; o <<= 1) {
            s0 += __shfl_xor_sync(~0u, s0, o);
            d0 += __shfl_xor_sync(~0u, d0, o);
            s1 += __shfl_xor_sync(~0u, s1, o);
            d1 += __shfl_xor_sync(~0u, d1, o);
        }
        if (t4 == 0) {
            if (r0 < M) {
                atomicAdd(&as_out[r0], s0);
                atomicAdd(&ad_out[r0], d0);
            }
            if (r1 < M) {
                atomicAdd(&as_out[r1], s1);
                atomicAdd(&ad_out[r1], d1);
            }
        }
    }
}

// ---------------- per-edge partial alpha: as[src] + aev --------------------
__global__ void edge_partial_kernel(const float* __restrict__ aev,
                                    const float* __restrict__ asv, int E) {
    for (int i = blockIdx.x * blockDim.x + threadIdx.x; i < E;
         i += gridDim.x * blockDim.x)
        d_alpha[i] = asv[d_csr_src[i]] + aev[i];
}

__device__ __forceinline__ float leaky(float x) {
    return fmaxf(x, NEG_SLOPE * x);
}

// ---------------- warp-per-node softmax (no max pass) + aggregation --------
template <int C, bool RELU>
__global__ void aggregate_kernel(const float* __restrict__ h,
                                 const float* __restrict__ bias,
                                 float* __restrict__ out,
                                 const float* __restrict__ asv,
                                 const float* __restrict__ adv, int N,
                                 int layer) {
    int warp = (blockIdx.x * blockDim.x + threadIdx.x) >> 5;
    int lane = threadIdx.x & 31;
    if (warp >= N) return;
    const int n = warp;
    const int rs = d_row[n], re = d_row[n + 1];
    const float adn = adv[n];
    float eself = __expf(leaky(asv[n] + adn + d_loopae[layer]));
    // sum of exp (logits are O(1); no max-subtraction needed)
    float ssum = 0.f;
    for (int j = rs + lane; j < re; j += 32)
        ssum += __expf(leaky(d_alpha[j] + adn));
    for (int o = 16; o; o >>= 1) ssum += __shfl_xor_sync(~0u, ssum, o);
    float inv = 1.f / (ssum + eself);

    constexpr int V = C / 128;  // float4s per lane
    float4 acc[V];
    {
        const float4* hn = (const float4*)(h + (size_t)n * C);
        float w = eself * inv;
#pragma unroll
        for (int k = 0; k < V; k++) {
            float4 hv = hn[lane + 32 * k];
            acc[k] = make_float4(hv.x * w, hv.y * w, hv.z * w, hv.w * w);
        }
    }
    for (int j = rs; j < re; j++) {
        float a = d_alpha[j];  // warp-broadcast load
        int s = d_csr_src[j];
        float w = __expf(leaky(a + adn)) * inv;
        const float4* hs = (const float4*)(h + (size_t)s * C);
#pragma unroll
        for (int k = 0; k < V; k++) {
            float4 hv = hs[lane + 32 * k];
            acc[k].x += w * hv.x;
            acc[k].y += w * hv.y;
            acc[k].z += w * hv.z;
            acc[k].w += w * hv.w;
        }
    }
    const float4* bp = (const float4*)bias;
    float4* op = (float4*)(out + (size_t)n * C);
#pragma unroll
    for (int k = 0; k < V; k++) {
        float4 b = bp[lane + 32 * k];
        float4 o = make_float4(acc[k].x + b.x, acc[k].y + b.y,
                               acc[k].z + b.z, acc[k].w + b.w);
        if (RELU) {
            o.x = fmaxf(o.x, 0.f);
            o.y = fmaxf(o.y, 0.f);
            o.z = fmaxf(o.z, 0.f);
            o.w = fmaxf(o.w, 0.f);
        }
        op[lane + 32 * k] = o;
    }
}

// ---------------- launch ----------------------------------------------------
extern "C" void kernel_launch(void* const* d_in, const int* in_sizes, int n_in,
                              void* d_out, int out_size) {
    const float* x   = (const float*)d_in[0];
    const int*   ei  = (const int*)d_in[1];
    const float* ea  = (const float*)d_in[2];
    const float* W1  = (const float*)d_in[3];
    const float* We1 = (const float*)d_in[4];
    const float* as1 = (const float*)d_in[5];
    const float* ad1 = (const float*)d_in[6];
    const float* ae1 = (const float*)d_in[7];
    const float* b1  = (const float*)d_in[8];
    const float* W2  = (const float*)d_in[9];
    const float* We2 = (const float*)d_in[10];
    const float* as2 = (const float*)d_in[11];
    const float* ad2 = (const float*)d_in[12];
    const float* ae2 = (const float*)d_in[13];
    const float* b2  = (const float*)d_in[14];
    float* out = (float*)d_out;

    const int E = in_sizes[2] / ED;
    const int N = in_sizes[0] / CIN;
    const int* srcp = ei;
    const int* dstp = ei + E;

    void* p;
    cudaGetSymbolAddress(&p, d_h);      float* hbuf   = (float*)p;
    cudaGetSymbolAddress(&p, d_hidden); float* hidbuf = (float*)p;
    cudaGetSymbolAddress(&p, d_aev1);   float* aev1p  = (float*)p;
    cudaGetSymbolAddress(&p, d_aev2);   float* aev2p  = (float*)p;
    cudaGetSymbolAddress(&p, d_as1);    float* as1p   = (float*)p;
    cudaGetSymbolAddress(&p, d_ad1);    float* ad1p   = (float*)p;
    cudaGetSymbolAddress(&p, d_as2);    float* as2p   = (float*)p;
    cudaGetSymbolAddress(&p, d_ad2);    float* ad2p   = (float*)p;

    const int TPB = 256;
    const int warpsPerBlock = TPB / 32;
    const int nodeBlocks = (N + warpsPerBlock - 1) / warpsPerBlock;

    // 1-3: structure build prologue (zero_v NEEDS 512 threads: 16 warps for v)
    zero_v_kernel<<<128, 512>>>(We1, ae1, We2, ae2, N);
    hist_kernel<<<512, TPB>>>(dstp, ea, E);
    scan_kernel<<<1, 1024>>>(N, 1.f / (float)E);

    // 4: layer-1 GEMM (+fused dots) — 4th launch, profiled by ncu
    {
        dim3 g(CHID / 128, (N + 127) / 128);
        mma_gemm_kernel<128, 128, 64, 32><<<g, 256>>>(
            x, W1, hbuf, as1, ad1, as1p, ad1p, N, CHID, CIN);
    }
    // 5: CSR scatter (independent of GEMM)
    scatter_kernel<<<512, TPB>>>(srcp, dstp, E);

    // 6-7: layer-1 edge pipeline
    edge_partial_kernel<<<512, TPB>>>(aev1p, as1p, E);
    aggregate_kernel<CHID, true><<<nodeBlocks, TPB>>>(hbuf, b1, hidbuf, as1p,
                                                      ad1p, N, 0);

    // 8: layer-2 GEMM (+fused dots) — BM=64 for better tail occupancy
    {
        dim3 g(COUT / 128, (N + 63) / 64);
        mma_gemm_kernel<64, 128, 32, 32><<<g, 256>>>(
            hidbuf, W2, hbuf, as2, ad2, as2p, ad2p, N, COUT, CHID);
    }
    // 9-10: layer-2 edge pipeline
    edge_partial_kernel<<<512, TPB>>>(aev2p, as2p, E);
    aggregate_kernel<COUT, false><<<nodeBlocks, TPB>>>(hbuf, b2, out, as2p,
                                                       ad2p, N, 1);
}

// round 5
// speedup vs baseline: 1.5889x; 1.1228x over previous
#include <cuda_runtime.h>
#include <cuda_fp16.h>
#include <cstdint>

#define NEG_SLOPE 0.2f

static constexpr int MAXN = 50000;
static constexpr int MAXE = 800000;
static constexpr int CIN  = 128;
static constexpr int CHID = 256;
static constexpr int COUT = 128;
static constexpr int ED   = 8;

// ---------------- scratch (static device globals; no allocation allowed) ---
__device__ int    d_deg[MAXN];
__device__ int    d_row[MAXN + 1];
__device__ int    d_cur[MAXN];
__device__ int    d_csr_src[MAXE];
__device__ float  d_tmpa[MAXE];   // edge-ordered aev1
__device__ float  d_tmpb[MAXE];   // edge-ordered aev2
__device__ float  d_aev1[MAXE];   // CSR-ordered
__device__ float  d_aev2[MAXE];
__device__ float  d_alpha[MAXE];  // exp(leaky(logit)) per CSR edge
__device__ __half d_hh[(size_t)MAXN * CHID];    // fp16 transformed feats
__device__ float  d_hidden[(size_t)MAXN * CHID];
__device__ float  d_as1[MAXN];
__device__ float  d_ad1[MAXN];
__device__ float  d_as2[MAXN];
__device__ float  d_ad2[MAXN];
__device__ float  d_easum[ED];
__device__ float  d_v[2][ED];
__device__ float  d_loopae[2];

// ---------------- zero + compute v (MUST run with >=512 threads/block) -----
__global__ void zero_v_kernel(const float* __restrict__ We1,
                              const float* __restrict__ ae1,
                              const float* __restrict__ We2,
                              const float* __restrict__ ae2, int n) {
    for (int i = blockIdx.x * blockDim.x + threadIdx.x; i < n;
         i += gridDim.x * blockDim.x) {
        d_deg[i] = 0;
        d_as1[i] = 0.f; d_ad1[i] = 0.f;
        d_as2[i] = 0.f; d_ad2[i] = 0.f;
    }
    if (blockIdx.x == 0) {
        if (threadIdx.x < ED) d_easum[threadIdx.x] = 0.f;
        int wid = threadIdx.x >> 5, lane = threadIdx.x & 31;
        if (wid < ED) {
            float s = 0.f;
            for (int c = lane; c < CHID; c += 32) s += We1[wid * CHID + c] * ae1[c];
            for (int o = 16; o; o >>= 1) s += __shfl_xor_sync(~0u, s, o);
            if (!lane) d_v[0][wid] = s;
        } else if (wid < 2 * ED) {
            int r = wid - ED;
            float s = 0.f;
            for (int c = lane; c < COUT; c += 32) s += We2[r * COUT + c] * ae2[c];
            for (int o = 16; o; o >>= 1) s += __shfl_xor_sync(~0u, s, o);
            if (!lane) d_v[1][r] = s;
        }
    }
}

// histogram of dst degrees + easum + per-edge attr attention (both layers)
__global__ void hist_kernel(const int* __restrict__ dstp,
                            const float* __restrict__ ea, int E) {
    __shared__ float ss[ED];
    if (threadIdx.x < ED) ss[threadIdx.x] = 0.f;
    __syncthreads();
    float v1[ED], v2[ED];
#pragma unroll
    for (int k = 0; k < ED; k++) { v1[k] = d_v[0][k]; v2[k] = d_v[1][k]; }
    float ls[ED] = {};
    for (int i = blockIdx.x * blockDim.x + threadIdx.x; i < E;
         i += gridDim.x * blockDim.x) {
        atomicAdd(&d_deg[dstp[i]], 1);
        const float4* p = (const float4*)(ea + (size_t)i * ED);
        float4 a = p[0], b = p[1];
        ls[0] += a.x; ls[1] += a.y; ls[2] += a.z; ls[3] += a.w;
        ls[4] += b.x; ls[5] += b.y; ls[6] += b.z; ls[7] += b.w;
        d_tmpa[i] = a.x * v1[0] + a.y * v1[1] + a.z * v1[2] + a.w * v1[3] +
                    b.x * v1[4] + b.y * v1[5] + b.z * v1[6] + b.w * v1[7];
        d_tmpb[i] = a.x * v2[0] + a.y * v2[1] + a.z * v2[2] + a.w * v2[3] +
                    b.x * v2[4] + b.y * v2[5] + b.z * v2[6] + b.w * v2[7];
    }
#pragma unroll
    for (int k = 0; k < ED; k++) atomicAdd(&ss[k], ls[k]);
    __syncthreads();
    if (threadIdx.x < ED) atomicAdd(&d_easum[threadIdx.x], ss[threadIdx.x]);
}

// single-block exclusive scan of d_deg -> d_row / d_cur ; + loopae
__global__ void scan_kernel(int n, float Einv) {
    __shared__ int partial[1024];
    const int t = threadIdx.x;
    const int CHK = (n + 1023) / 1024;
    int start = t * CHK;
    int end = start + CHK; if (end > n) end = n;
    int s = 0;
    for (int i = start; i < end; i++) s += d_deg[i];
    partial[t] = s;
    __syncthreads();
    for (int off = 1; off < 1024; off <<= 1) {
        int v = (t >= off) ? partial[t - off] : 0;
        __syncthreads();
        partial[t] += v;
        __syncthreads();
    }
    int run = (t == 0) ? 0 : partial[t - 1];
    for (int i = start; i < end; i++) {
        d_row[i] = run;
        d_cur[i] = run;
        run += d_deg[i];
    }
    if (t == 1023) d_row[n] = partial[1023];
    if (t < 2) {
        float la = 0.f;
#pragma unroll
        for (int i = 0; i < ED; i++) la += d_easum[i] * Einv * d_v[t][i];
        d_loopae[t] = la;
    }
}

// scatter edges into CSR-by-dst; permute precomputed aev
__global__ void scatter_kernel(const int* __restrict__ srcp,
                               const int* __restrict__ dstp, int E) {
    for (int e = blockIdx.x * blockDim.x + threadIdx.x; e < E;
         e += gridDim.x * blockDim.x) {
        int d = dstp[e];
        int pos = atomicAdd(&d_cur[d], 1);
        d_csr_src[pos] = srcp[e];
        d_aev1[pos] = d_tmpa[e];
        d_aev2[pos] = d_tmpb[e];
    }
}

// ---------------- tf32 tensor-core GEMM + fused attention dots -------------
__device__ __forceinline__ uint32_t f2tf32(float x) {
    uint32_t u;
    asm("cvt.rna.tf32.f32 %0, %1;" : "=r"(u) : "f"(x));
    return u;
}
__device__ __forceinline__ void mma_tf32(float* d, const uint32_t* a,
                                         const uint32_t* b) {
    asm volatile(
        "mma.sync.aligned.m16n8k8.row.col.f32.tf32.tf32.f32 "
        "{%0,%1,%2,%3}, {%4,%5,%6,%7}, {%8,%9}, {%0,%1,%2,%3};\n"
        : "+f"(d[0]), "+f"(d[1]), "+f"(d[2]), "+f"(d[3])
        : "r"(a[0]), "r"(a[1]), "r"(a[2]), "r"(a[3]), "r"(b[0]), "r"(b[1]));
}

// Ch[M,N] = half(A[M,K] @ B[K,N]); fused dots on fp32 acc:
// as_out[m] += sum_c C[m,c]*av[c], ad_out[m] += sum_c C[m,c]*dv[c]
template <int BM, int BN, int WM, int WN>
__global__ __launch_bounds__(256, 2) void mma_gemm_kernel(
    const float* __restrict__ A, const float* __restrict__ B,
    __half* __restrict__ Ch, const float* __restrict__ av,
    const float* __restrict__ dv, float* __restrict__ as_out,
    float* __restrict__ ad_out, int M, int N, int K) {
    constexpr int GBK = 16;
    constexpr int AP = GBK + 4;
    constexpr int BP = BN + 8;
    constexpr int WCOLS = BN / WN;
    constexpr int MI = WM / 16;
    constexpr int NJ = WN / 8;
    constexpr int LA = BM / 64;
    constexpr int LB = BN / 64;

    __shared__ __align__(16) uint32_t As[2][BM][AP];
    __shared__ __align__(16) uint32_t Bs[2][GBK][BP];

    const int t = threadIdx.x;
    const int bm = blockIdx.y * BM;
    const int bn = blockIdx.x * BN;
    const int warp = t >> 5, lane = t & 31;
    const int g = lane >> 2, t4 = lane & 3;
    const int wm = (warp / WCOLS) * WM, wn = (warp % WCOLS) * WN;

    float4 pa[LA], pb[LB];
    auto ldg = [&](int k0) {
#pragma unroll
        for (int r = 0; r < LA; r++) {
            int id = t + 256 * r;
            int row = id >> 2, col = (id & 3) * 4;
            int gr = bm + row;
            pa[r] = (gr < M) ? *(const float4*)(A + (size_t)gr * K + k0 + col)
                             : make_float4(0.f, 0.f, 0.f, 0.f);
        }
#pragma unroll
        for (int r = 0; r < LB; r++) {
            int id = t + 256 * r;
            int row = id / (BN / 4), col = (id % (BN / 4)) * 4;
            pb[r] = *(const float4*)(B + (size_t)(k0 + row) * N + bn + col);
        }
    };
    auto sts = [&](int s) {
#pragma unroll
        for (int r = 0; r < LA; r++) {
            int id = t + 256 * r;
            int row = id >> 2, col = (id & 3) * 4;
            uint4 u;
            u.x = f2tf32(pa[r].x); u.y = f2tf32(pa[r].y);
            u.z = f2tf32(pa[r].z); u.w = f2tf32(pa[r].w);
            *(uint4*)&As[s][row][col] = u;
        }
#pragma unroll
        for (int r = 0; r < LB; r++) {
            int id = t + 256 * r;
            int row = id / (BN / 4), col = (id % (BN / 4)) * 4;
            uint4 u;
            u.x = f2tf32(pb[r].x); u.y = f2tf32(pb[r].y);
            u.z = f2tf32(pb[r].z); u.w = f2tf32(pb[r].w);
            *(uint4*)&Bs[s][row][col] = u;
        }
    };

    float acc[MI][NJ][4];
#pragma unroll
    for (int i = 0; i < MI; i++)
#pragma unroll
        for (int j = 0; j < NJ; j++)
#pragma unroll
            for (int r = 0; r < 4; r++) acc[i][j][r] = 0.f;

    const int nIter = K / GBK;
    ldg(0);
    sts(0);
    __syncthreads();

    for (int it = 0; it < nIter; it++) {
        const int s = it & 1;
        if (it + 1 < nIter) ldg((it + 1) * GBK);
#pragma unroll
        for (int kk = 0; kk < 2; kk++) {
            uint32_t af[MI][4], bf[NJ][2];
#pragma unroll
            for (int i = 0; i < MI; i++) {
                int r0 = wm + i * 16 + g;
                af[i][0] = As[s][r0][kk * 8 + t4];
                af[i][1] = As[s][r0 + 8][kk * 8 + t4];
                af[i][2] = As[s][r0][kk * 8 + t4 + 4];
                af[i][3] = As[s][r0 + 8][kk * 8 + t4 + 4];
            }
#pragma unroll
            for (int j = 0; j < NJ; j++) {
                bf[j][0] = Bs[s][kk * 8 + t4][wn + j * 8 + g];
                bf[j][1] = Bs[s][kk * 8 + t4 + 4][wn + j * 8 + g];
            }
#pragma unroll
            for (int i = 0; i < MI; i++)
#pragma unroll
                for (int j = 0; j < NJ; j++) mma_tf32(acc[i][j], af[i], bf[j]);
        }
        if (it + 1 < nIter) {
            sts(s ^ 1);
            __syncthreads();
        }
    }

    // epilogue: half store + fused partial dots into as/ad via atomics
#pragma unroll
    for (int i = 0; i < MI; i++) {
        int r0 = bm + wm + i * 16 + g;
        int r1 = r0 + 8;
        float s0 = 0.f, d0 = 0.f, s1 = 0.f, d1 = 0.f;
#pragma unroll
        for (int j = 0; j < NJ; j++) {
            int c = bn + wn + j * 8 + 2 * t4;
            float a0 = av[c], a1 = av[c + 1];
            float e0 = dv[c], e1 = dv[c + 1];
            s0 += acc[i][j][0] * a0 + acc[i][j][1] * a1;
            d0 += acc[i][j][0] * e0 + acc[i][j][1] * e1;
            s1 += acc[i][j][2] * a0 + acc[i][j][3] * a1;
            d1 += acc[i][j][2] * e0 + acc[i][j][3] * e1;
            if (r0 < M)
                *(__half2*)(Ch + (size_t)r0 * N + c) =
                    __floats2half2_rn(acc[i][j][0], acc[i][j][1]);
            if (r1 < M)
                *(__half2*)(Ch + (size_t)r1 * N + c) =
                    __floats2half2_rn(acc[i][j][2], acc[i][j][3]);
        }
#pragma unroll
        for (int o = 1; o < 4; o <<= 1) {
            s0 += __shfl_xor_sync(~0u, s0, o);
            d0 += __shfl_xor_sync(~0u, d0, o);
            s1 += __shfl_xor_sync(~0u, s1, o);
            d1 += __shfl_xor_sync(~0u, d1, o);
        }
        if (t4 == 0) {
            if (r0 < M) {
                atomicAdd(&as_out[r0], s0);
                atomicAdd(&ad_out[r0], d0);
            }
            if (r1 < M) {
                atomicAdd(&as_out[r1], s1);
                atomicAdd(&ad_out[r1], d1);
            }
        }
    }
}

__device__ __forceinline__ float leaky(float x) {
    return fmaxf(x, NEG_SLOPE * x);
}

// -------- warp-per-node fused alpha + softmax + fp16 gather aggregation ----
template <int C, bool RELU>
__global__ void aggregate_kernel(const __half* __restrict__ hh,
                                 const float* __restrict__ bias,
                                 float* __restrict__ out,
                                 const float* __restrict__ asv,
                                 const float* __restrict__ adv,
                                 const float* __restrict__ aev, int N,
                                 int layer) {
    int warp = (blockIdx.x * blockDim.x + threadIdx.x) >> 5;
    int lane = threadIdx.x & 31;
    if (warp >= N) return;
    const int n = warp;
    const int rs = d_row[n], re = d_row[n + 1];
    const float adn = adv[n];
    float eself = __expf(leaky(asv[n] + adn + d_loopae[layer]));
    // pass 1: per-edge exp(leaky(logit)), lane-parallel; logits are O(1)
    float ssum = 0.f;
    for (int j = rs + lane; j < re; j += 32) {
        int s = d_csr_src[j];
        float ex = __expf(leaky(asv[s] + aev[j] + adn));
        d_alpha[j] = ex;
        ssum += ex;
    }
    for (int o = 16; o; o >>= 1) ssum += __shfl_xor_sync(~0u, ssum, o);
    __syncwarp();  // fence d_alpha stores before cross-lane reads
    float inv = 1.f / (ssum + eself);

    constexpr int NH2 = C / 64;  // half2 per lane (4 for C=256, 2 for C=128)
    float acc[2 * NH2];
    union U4 { uint4 v; __half2 h2[4]; };
    union U2 { uint2 v; __half2 h2[2]; };
    {
        float w = eself * inv;
        if constexpr (C == 256) {
            U4 r; r.v = ((const uint4*)(hh + (size_t)n * C))[lane];
#pragma unroll
            for (int k = 0; k < 4; k++) {
                float2 f = __half22float2(r.h2[k]);
                acc[2 * k] = w * f.x;
                acc[2 * k + 1] = w * f.y;
            }
        } else {
            U2 r; r.v = ((const uint2*)(hh + (size_t)n * C))[lane];
#pragma unroll
            for (int k = 0; k < 2; k++) {
                float2 f = __half22float2(r.h2[k]);
                acc[2 * k] = w * f.x;
                acc[2 * k + 1] = w * f.y;
            }
        }
    }
    for (int j = rs; j < re; j++) {
        float w = d_alpha[j] * inv;   // warp-broadcast load
        int s = d_csr_src[j];
        if constexpr (C == 256) {
            U4 r; r.v = ((const uint4*)(hh + (size_t)s * C))[lane];
#pragma unroll
            for (int k = 0; k < 4; k++) {
                float2 f = __half22float2(r.h2[k]);
                acc[2 * k] += w * f.x;
                acc[2 * k + 1] += w * f.y;
            }
        } else {
            U2 r; r.v = ((const uint2*)(hh + (size_t)s * C))[lane];
#pragma unroll
            for (int k = 0; k < 2; k++) {
                float2 f = __half22float2(r.h2[k]);
                acc[2 * k] += w * f.x;
                acc[2 * k + 1] += w * f.y;
            }
        }
    }
    // write out: lane owns columns [lane*2*NH2, lane*2*NH2 + 2*NH2)
    const int base = lane * 2 * NH2;
    float* op = out + (size_t)n * C + base;
    const float* bp = bias + base;
#pragma unroll
    for (int k = 0; k < 2 * NH2; k += 4) {
        float4 b = *(const float4*)(bp + k);
        float4 o = make_float4(acc[k] + b.x, acc[k + 1] + b.y,
                               acc[k + 2] + b.z, acc[k + 3] + b.w);
        if (RELU) {
            o.x = fmaxf(o.x, 0.f);
            o.y = fmaxf(o.y, 0.f);
            o.z = fmaxf(o.z, 0.f);
            o.w = fmaxf(o.w, 0.f);
        }
        *(float4*)(op + k) = o;
    }
}

// ---------------- launch ----------------------------------------------------
extern "C" void kernel_launch(void* const* d_in, const int* in_sizes, int n_in,
                              void* d_out, int out_size) {
    const float* x   = (const float*)d_in[0];
    const int*   ei  = (const int*)d_in[1];
    const float* ea  = (const float*)d_in[2];
    const float* W1  = (const float*)d_in[3];
    const float* We1 = (const float*)d_in[4];
    const float* as1 = (const float*)d_in[5];
    const float* ad1 = (const float*)d_in[6];
    const float* ae1 = (const float*)d_in[7];
    const float* b1  = (const float*)d_in[8];
    const float* W2  = (const float*)d_in[9];
    const float* We2 = (const float*)d_in[10];
    const float* as2 = (const float*)d_in[11];
    const float* ad2 = (const float*)d_in[12];
    const float* ae2 = (const float*)d_in[13];
    const float* b2  = (const float*)d_in[14];
    float* out = (float*)d_out;

    const int E = in_sizes[2] / ED;
    const int N = in_sizes[0] / CIN;
    const int* srcp = ei;
    const int* dstp = ei + E;

    void* p;
    cudaGetSymbolAddress(&p, d_hh);     __half* hhp   = (__half*)p;
    cudaGetSymbolAddress(&p, d_hidden); float* hidbuf = (float*)p;
    cudaGetSymbolAddress(&p, d_aev1);   float* aev1p  = (float*)p;
    cudaGetSymbolAddress(&p, d_aev2);   float* aev2p  = (float*)p;
    cudaGetSymbolAddress(&p, d_as1);    float* as1p   = (float*)p;
    cudaGetSymbolAddress(&p, d_ad1);    float* ad1p   = (float*)p;
    cudaGetSymbolAddress(&p, d_as2);    float* as2p   = (float*)p;
    cudaGetSymbolAddress(&p, d_ad2);    float* ad2p   = (float*)p;

    const int TPB = 256;
    const int warpsPerBlock = TPB / 32;
    const int nodeBlocks = (N + warpsPerBlock - 1) / warpsPerBlock;

    // 1-3: structure build prologue (zero_v NEEDS 512 threads: 16 warps for v)
    zero_v_kernel<<<128, 512>>>(We1, ae1, We2, ae2, N);
    hist_kernel<<<512, TPB>>>(dstp, ea, E);
    scan_kernel<<<1, 1024>>>(N, 1.f / (float)E);

    // 4: layer-1 GEMM (+fused dots, half output) — 4th launch for ncu
    {
        dim3 g(CHID / 128, (N + 127) / 128);
        mma_gemm_kernel<128, 128, 64, 32><<<g, 256>>>(
            x, W1, hhp, as1, ad1, as1p, ad1p, N, CHID, CIN);
    }
    // 5: CSR scatter (independent of GEMM)
    scatter_kernel<<<512, TPB>>>(srcp, dstp, E);

    // 6: layer-1 fused alpha+softmax+aggregate (fp16 gather)
    aggregate_kernel<CHID, true><<<nodeBlocks, TPB>>>(hhp, b1, hidbuf, as1p,
                                                      ad1p, aev1p, N, 0);

    // 7: layer-2 GEMM (+fused dots, half output)
    {
        dim3 g(COUT / 128, (N + 63) / 64);
        mma_gemm_kernel<64, 128, 32, 32><<<g, 256>>>(
            hidbuf, W2, hhp, as2, ad2, as2p, ad2p, N, COUT, CHID);
    }
    // 8: layer-2 fused aggregate
    aggregate_kernel<COUT, false><<<nodeBlocks, TPB>>>(hhp, b2, out, as2p,
                                                       ad2p, aev2p, N, 1);
}